// round 15
// baseline (speedup 1.0000x reference)
#include <cuda_runtime.h>
#include <cstdint>

typedef unsigned long long u64;

#define NV    64          // vertices
#define NC    64          // channels (in = out)
#define LTOT  512
#define PADC  129         // float2 row stride (64*2 cols + 1 pad) -> odd word stride
#define NTHR  256
#define NSLAB 4           // slabs of 4 l per CTA  -> 16 l per CTA

// smem float layout: a(4096) a2(4096) M0(4096) M1(4096) M2(4096)
#define OPS_FLOATS 20480
#define BUF_F2     (64 * PADC)                              // 8256 float2 per buffer
#define SMEM_BYTES (OPS_FLOATS * 4 + 2 * BUF_F2 * 8)        // 214016 bytes

// Precomputed operators (device globals: no allocation allowed)
// [0]=a  [4096]=a2  [8192]=M0  [12288]=M1  [16384]=M2
__device__ float g_ops[OPS_FLOATS];

// ---------------------------------------------------------------------------
// Setup: a = rownorm(adj + I); a2 = a*a; fold alpha-mixing into W -> M0,M1,M2
// out = M0*X + M1*(A X) + M2*(A^2 X) + b
// ---------------------------------------------------------------------------
__global__ void mixprop_setup_kernel(const float* __restrict__ adj,
                                     const float* __restrict__ W)
{
    __shared__ float s_a[64 * 64];
    __shared__ float dinv[64];
    const int t = threadIdx.x;                   // 256 threads
    if (t < 64) {
        float s = 1.0f;                          // identity diagonal contribution
        #pragma unroll 8
        for (int w = 0; w < 64; ++w) s += adj[t * 64 + w];
        dinv[t] = 1.0f / s;
    }
    __syncthreads();
    for (int i = t; i < 4096; i += 256) {
        const int v = i >> 6, w = i & 63;
        float av = (adj[i] + (v == w ? 1.0f : 0.0f)) * dinv[v];
        s_a[i]   = av;
        g_ops[i] = av;                           // a
    }
    __syncthreads();
    for (int i = t; i < 4096; i += 256) {        // a2 = a @ a
        const int v = i >> 6, w = i & 63;
        float s = 0.0f;
        #pragma unroll 8
        for (int u = 0; u < 64; ++u) s += s_a[v * 64 + u] * s_a[u * 64 + w];
        g_ops[4096 + i] = s;
    }
    const float A = 0.05f, OMA = 0.95f;
    for (int i = t; i < 4096; i += 256) {
        const int o = i >> 6, c = i & 63;
        const float w0 = W[o * 192 + c];
        const float w1 = W[o * 192 + 64 + c];
        const float w2 = W[o * 192 + 128 + c];
        g_ops[ 8192 + i] = w0 + A * (w1 + w2);       // M0
        g_ops[12288 + i] = OMA * (w1 + A * w2);      // M1
        g_ops[16384 + i] = OMA * OMA * w2;           // M2
    }
}

// ---------------------------------------------------------------------------
// f32x2 + cp.async helpers
// ---------------------------------------------------------------------------
__device__ __forceinline__ u64 pack2(float s) {
    u64 r;
    asm("mov.b64 %0, {%1, %1};" : "=l"(r) : "f"(s));
    return r;
}
__device__ __forceinline__ void fma2(u64& d, u64 a, u64 b) {
    asm("fma.rn.f32x2 %0, %1, %2, %0;" : "+l"(d) : "l"(a), "l"(b));
}
__device__ __forceinline__ void cp_async8(float2* smem_dst, const float* gsrc) {
    uint32_t s = (uint32_t)__cvta_generic_to_shared(smem_dst);
    asm volatile("cp.async.ca.shared.global [%0], [%1], 8;" :: "r"(s), "l"(gsrc));
}
__device__ __forceinline__ void cp_commit() {
    asm volatile("cp.async.commit_group;");
}
__device__ __forceinline__ void cp_wait0() {
    asm volatile("cp.async.wait_group 0;" ::: "memory");
}

// ---------------------------------------------------------------------------
// Channel GEMM: acc[o][(v,jp)] += M[o][c] * B[c][(v,jp)]   (row-contig B reads)
// thread tile: m = m0..m0+7 (o), n = tx + 32*i  i=0..3
// ---------------------------------------------------------------------------
__device__ __forceinline__ void gemmC(const float* __restrict__ Am,
                                      const float2* __restrict__ B,
                                      u64* acc, int m0, const int* nIdx)
{
    #pragma unroll 2
    for (int k2 = 0; k2 < 32; ++k2) {
        float2 af[8];
        #pragma unroll
        for (int im = 0; im < 8; ++im)
            af[im] = *(const float2*)(Am + (m0 + im) * 64 + k2 * 2);
        #pragma unroll
        for (int kk = 0; kk < 2; ++kk) {
            const int k = k2 * 2 + kk;
            u64 bb[4];
            #pragma unroll
            for (int i = 0; i < 4; ++i)
                bb[i] = *(const u64*)(B + k * PADC + nIdx[i]);
            #pragma unroll
            for (int im = 0; im < 8; ++im) {
                const u64 a2 = pack2(kk == 0 ? af[im].x : af[im].y);
                #pragma unroll
                for (int i = 0; i < 4; ++i)
                    fma2(acc[im * 4 + i], a2, bb[i]);
            }
        }
    }
}

// ---------------------------------------------------------------------------
// Vertex GEMM: y[v][(c,jp)] = sum_w a[v][w] * B[c][(w,jp)]  (transposed reads)
// ---------------------------------------------------------------------------
__device__ __forceinline__ void gemmV(const float* __restrict__ Am,
                                      const float2* __restrict__ B,
                                      u64* acc, int m0, const int* cOff)
{
    #pragma unroll
    for (int j = 0; j < 32; ++j) acc[j] = 0ULL;
    #pragma unroll 2
    for (int k2 = 0; k2 < 32; ++k2) {
        float2 af[8];
        #pragma unroll
        for (int im = 0; im < 8; ++im)
            af[im] = *(const float2*)(Am + (m0 + im) * 64 + k2 * 2);
        #pragma unroll
        for (int kk = 0; kk < 2; ++kk) {
            const int k = k2 * 2 + kk;
            u64 bb[4];
            #pragma unroll
            for (int i = 0; i < 4; ++i)
                bb[i] = *(const u64*)(B + cOff[i] + k * 2);
            #pragma unroll
            for (int im = 0; im < 8; ++im) {
                const u64 a2 = pack2(kk == 0 ? af[im].x : af[im].y);
                #pragma unroll
                for (int i = 0; i < 4; ++i)
                    fma2(acc[im * 4 + i], a2, bb[i]);
            }
        }
    }
}

// store gemmV result y[v][(c,jp)] into buffer layout [c][(v,jp)]
__device__ __forceinline__ void storeY(float2* __restrict__ Bdst,
                                       const u64* acc, int m0, const int* cOff)
{
    #pragma unroll
    for (int im = 0; im < 8; ++im)
        #pragma unroll
        for (int i = 0; i < 4; ++i)
            *(u64*)(Bdst + cOff[i] + (m0 + im) * 2) = acc[im * 4 + i];
}

// async-load one 4-l slab of X into buf: layout [c][v*2+jp] of float2
__device__ __forceinline__ void loadSlabAsync(float2* __restrict__ buf,
                                              const float* __restrict__ xn,
                                              int l0, int tid)
{
    #pragma unroll
    for (int r = 0; r < 32; ++r) {
        const int idx = tid + NTHR * r;        // 0..8191
        const int c   = idx >> 7;
        const int col = idx & 127;
        const int v   = col >> 1;
        const int jp  = col & 1;
        cp_async8(buf + c * PADC + col,
                  xn + ((c * NV + v) * LTOT) + l0 + jp * 2);
    }
}

// ---------------------------------------------------------------------------
// Fused main kernel: one CTA = one (n, 16-l chunk); NSLAB slabs of 4 l.
// Per slab:
//   P2: out=b+M0*X ; Y1=A*X -> sB1          (reads sB0)
//   P3: out+=M1*Y1 ; Y2=A2*X (regs)         (reads sB1, sB0)   [indep streams]
//   prefetch next X -> sB0 (cp.async, overlaps P4+P5)
//   P4: publish Y2 -> sB1
//   P5: out+=M2*Y2 ; store out
// ---------------------------------------------------------------------------
__global__ void __launch_bounds__(NTHR, 1)
mixprop_main_kernel(const float* __restrict__ x,
                    const float* __restrict__ bias,
                    float* __restrict__ out)
{
    extern __shared__ float smem[];
    float*  sA   = smem;                       // a
    float*  sA2  = smem + 4096;                // a^2
    float*  sM0  = smem + 8192;
    float*  sM1  = smem + 12288;
    float*  sM2  = smem + 16384;
    float2* sB0  = (float2*)(smem + OPS_FLOATS);
    float2* sB1  = sB0 + BUF_F2;

    const int tid = threadIdx.x;

    const int    n      = blockIdx.y;
    const size_t baseNC = (size_t)n * (NC * NV * LTOT);
    const float* xn     = x + baseNC;
    float*       outn   = out + baseNC;
    const int    l0base = blockIdx.x * (4 * NSLAB);

    // prefetch slab 0 while staging the five 64x64 operators (80KB)
    loadSlabAsync(sB0, xn, l0base, tid);
    cp_commit();
    {
        float4*       d = (float4*)smem;
        const float4* g = (const float4*)g_ops;
        #pragma unroll
        for (int i = 0; i < 20; ++i) d[tid + NTHR * i] = g[tid + NTHR * i];
    }

    const int tx = tid & 31;
    const int ty = tid >> 5;           // 0..7
    const int m0 = ty * 8;

    int nIdx[4], cOff[4];
    #pragma unroll
    for (int i = 0; i < 4; ++i) {
        nIdx[i] = tx + 32 * i;                             // col = v*2 + jp
        cOff[i] = (nIdx[i] >> 1) * PADC + (nIdx[i] & 1);   // transposed base
    }

    u64 bpack[8];
    #pragma unroll
    for (int im = 0; im < 8; ++im) bpack[im] = pack2(bias[m0 + im]);

    u64 outAcc[32], yAcc[32];

    cp_wait0();
    __syncthreads();   // operators staged + slab 0 resident

    #pragma unroll 1
    for (int it = 0; it < NSLAB; ++it) {
        const int l0 = l0base + it * 4;

        // P2: out = b + M0*X ;  Y1 = A*X -> sB1
        #pragma unroll
        for (int im = 0; im < 8; ++im)
            #pragma unroll
            for (int i = 0; i < 4; ++i)
                outAcc[im * 4 + i] = bpack[im];
        gemmC(sM0, sB0, outAcc, m0, nIdx);
        gemmV(sA,  sB0, yAcc,   m0, cOff);
        storeY(sB1, yAcc, m0, cOff);
        __syncthreads();                      // (a) Y1 visible

        // P3: out += M1*Y1 ;  Y2 = A2*X  (two independent streams)
        gemmC(sM1, sB1, outAcc, m0, nIdx);
        gemmV(sA2, sB0, yAcc,   m0, cOff);
        __syncthreads();                      // (b) sB0 & sB1 reads complete

        // prefetch next slab's X over sB0 (overlaps P4 + P5)
        if (it + 1 < NSLAB) {
            loadSlabAsync(sB0, xn, l0 + 4, tid);
        }
        cp_commit();

        // P4: publish Y2 over sB1
        storeY(sB1, yAcc, m0, cOff);
        __syncthreads();                      // (c) Y2 visible

        // P5: out += M2*Y2 ; write out
        gemmC(sM2, sB1, outAcc, m0, nIdx);

        #pragma unroll
        for (int im = 0; im < 8; ++im) {
            const int o = m0 + im;
            #pragma unroll
            for (int i = 0; i < 4; ++i) {
                const int col = nIdx[i];
                const int v   = col >> 1;
                const int jp  = col & 1;
                *(u64*)(outn + ((o * NV + v) * LTOT) + l0 + jp * 2) = outAcc[im * 4 + i];
            }
        }
        cp_wait0();                           // next X landed
        __syncthreads();                      // (d) visible to all warps
    }
}

// ---------------------------------------------------------------------------
// Launch
// ---------------------------------------------------------------------------
extern "C" void kernel_launch(void* const* d_in, const int* in_sizes, int n_in,
                              void* d_out, int out_size)
{
    (void)in_sizes; (void)n_in; (void)out_size;
    const float* x   = (const float*)d_in[0];   // [32,64,64,512]
    const float* adj = (const float*)d_in[1];   // [64,64]
    const float* W   = (const float*)d_in[2];   // [64,192]
    const float* b   = (const float*)d_in[3];   // [64]
    float*       out = (float*)d_out;           // [32,64,64,512]

    mixprop_setup_kernel<<<1, 256>>>(adj, W);

    cudaFuncSetAttribute(mixprop_main_kernel,
                         cudaFuncAttributeMaxDynamicSharedMemorySize, SMEM_BYTES);

    dim3 grid(LTOT / (4 * NSLAB), 32);   // 32 l-chunks (16 l each) x 32 batch
    mixprop_main_kernel<<<grid, NTHR, SMEM_BYTES>>>(x, b, out);
}

// round 17
// speedup vs baseline: 1.0100x; 1.0100x over previous
#include <cuda_runtime.h>
#include <cuda_bf16.h>
#include <cstdint>

typedef unsigned int   u32;
typedef unsigned short u16;

#define LB   4            // l per CTA
#define PC   68           // u32 row stride of data buffers (rows = dim*4 + l)
#define POP  33           // operator row stride in u32 (32 + 1 pad)

// 8 operator tables, each u16[64][64] row-major [n][k]:
// 0 Ahi, 1 Alo, 2 M0hi, 3 M0lo, 4 M1hi, 5 M1lo, 6 M2hi, 7 M2lo
__device__ u32 g_opsU[8 * 2048];

__device__ __forceinline__ u16 bfh(float f) { return __bfloat16_as_ushort(__float2bfloat16_rn(f)); }
__device__ __forceinline__ float bff(u16 h) { return __bfloat162float(__ushort_as_bfloat16(h)); }
__device__ __forceinline__ u32 packHL(float f) {     // (hi<<16)|lo
    u16 h = bfh(f);
    u16 l = bfh(f - bff(h));
    return ((u32)h << 16) | l;
}

// ---------------------------------------------------------------------------
// Setup: a = rownorm(adj+I); fold alpha into W; emit bf16 hi/lo tables
// out = M0 X + M1 (A X) + M2 (A (A X)) + b
// ---------------------------------------------------------------------------
__global__ void setup_kernel(const float* __restrict__ adj, const float* __restrict__ W)
{
    __shared__ float dinv[64];
    const int t = threadIdx.x;                    // 256
    if (t < 64) {
        float s = 1.0f;
        for (int w = 0; w < 64; ++w) s += adj[t * 64 + w];
        dinv[t] = 1.0f / s;
    }
    __syncthreads();
    u16* ops = (u16*)g_opsU;
    for (int i = t; i < 4096; i += 256) {
        const int v = i >> 6, w = i & 63;
        const float av = (adj[i] + (v == w ? 1.0f : 0.0f)) * dinv[v];
        const u16 h = bfh(av);
        ops[i] = h;
        ops[4096 + i] = bfh(av - bff(h));
    }
    const float A = 0.05f, B = 0.95f;
    for (int i = t; i < 4096; i += 256) {
        const int o = i >> 6, c = i & 63;
        const float w0 = W[o*192 + c], w1 = W[o*192 + 64 + c], w2 = W[o*192 + 128 + c];
        const float m[3] = { w0 + A*(w1 + w2), B*(w1 + A*w2), B*B*w2 };
        #pragma unroll
        for (int s = 0; s < 3; ++s) {
            const u16 h = bfh(m[s]);
            ops[(2 + 2*s) * 4096 + i] = h;
            ops[(3 + 2*s) * 4096 + i] = bfh(m[s] - bff(h));
        }
    }
}

// ---------------------------------------------------------------------------
// mma.sync m16n8k16 bf16 (row.col), fp32 accumulate
// ---------------------------------------------------------------------------
#define MMA_BF16(d, a0,a1,a2,a3, b0,b1) \
    asm volatile("mma.sync.aligned.m16n8k16.row.col.f32.bf16.bf16.f32 " \
                 "{%0,%1,%2,%3},{%4,%5,%6,%7},{%8,%9},{%0,%1,%2,%3};" \
                 : "+f"(d[0]), "+f"(d[1]), "+f"(d[2]), "+f"(d[3]) \
                 : "r"(a0), "r"(a1), "r"(a2), "r"(a3), "r"(b0), "r"(b1))

// 3-term (hi*hi + lo*hi + hi*lo) GEMM: D[m=(dim,l)=256, n=64] += Bsrc * op^T.
// VERT=0: A-element (m, k) at Bs[m*PC + k]          (m=(v,l), k=c contiguous)
// VERT=1: A-element (m, k) at Bs[(k*4+(m&3))*PC + (m>>2)]  (m=(c,l), k=w)
template<int VERT>
__device__ __forceinline__ void gemm3(const u32* __restrict__ opHi,
                                      const u32* __restrict__ opLo,
                                      const u32* __restrict__ Bs,
                                      float (*D)[4], int wid, int g, int t)
{
    #pragma unroll 1
    for (int kt = 0; kt < 4; ++kt) {
        u32 bh0[8], bh1[8], bl0[8], bl1[8];
        #pragma unroll
        for (int nt = 0; nt < 8; ++nt) {
            const int r = (nt * 8 + g) * POP + kt * 8 + t;
            bh0[nt] = opHi[r]; bh1[nt] = opHi[r + 4];
            bl0[nt] = opLo[r]; bl1[nt] = opLo[r + 4];
        }
        #pragma unroll
        for (int mi = 0; mi < 2; ++mi) {
            const int m0 = (wid * 2 + mi) * 16 + g;
            const int k0 = kt * 16 + 2 * t;
            u32 w0, w1, w2, w3, w4, w5, w6, w7;
            if (VERT) {
                const int c0 = m0 >> 2, l_ = m0 & 3, c1 = (m0 + 8) >> 2;
                w0 = Bs[(k0*4 + l_)*PC + c0];     w1 = Bs[((k0+1)*4 + l_)*PC + c0];
                w2 = Bs[(k0*4 + l_)*PC + c1];     w3 = Bs[((k0+1)*4 + l_)*PC + c1];
                w4 = Bs[((k0+8)*4 + l_)*PC + c0]; w5 = Bs[((k0+9)*4 + l_)*PC + c0];
                w6 = Bs[((k0+8)*4 + l_)*PC + c1]; w7 = Bs[((k0+9)*4 + l_)*PC + c1];
            } else {
                w0 = Bs[m0*PC + k0];       w1 = Bs[m0*PC + k0 + 1];
                w2 = Bs[(m0+8)*PC + k0];   w3 = Bs[(m0+8)*PC + k0 + 1];
                w4 = Bs[m0*PC + k0 + 8];   w5 = Bs[m0*PC + k0 + 9];
                w6 = Bs[(m0+8)*PC + k0+8]; w7 = Bs[(m0+8)*PC + k0 + 9];
            }
            const u32 ah0 = __byte_perm(w0, w1, 0x7632), al0 = __byte_perm(w0, w1, 0x5410);
            const u32 ah1 = __byte_perm(w2, w3, 0x7632), al1 = __byte_perm(w2, w3, 0x5410);
            const u32 ah2 = __byte_perm(w4, w5, 0x7632), al2 = __byte_perm(w4, w5, 0x5410);
            const u32 ah3 = __byte_perm(w6, w7, 0x7632), al3 = __byte_perm(w6, w7, 0x5410);
            #pragma unroll
            for (int nt = 0; nt < 8; ++nt) {
                float* d = D[mi * 8 + nt];
                MMA_BF16(d, ah0, ah1, ah2, ah3, bh0[nt], bh1[nt]);
                MMA_BF16(d, al0, al1, al2, al3, bh0[nt], bh1[nt]);
                MMA_BF16(d, ah0, ah1, ah2, ah3, bl0[nt], bl1[nt]);
            }
        }
    }
}

// vertex result D[(c,l), v'] -> buffer rows (v'*4+l), col c, packed hi/lo
__device__ __forceinline__ void storeVert(u32* __restrict__ Bd, float (*VD)[4],
                                          int wid, int g, int t)
{
    #pragma unroll
    for (int mi = 0; mi < 2; ++mi) {
        const int m0 = (wid * 2 + mi) * 16 + g;
        const int c0 = m0 >> 2, l_ = m0 & 3, c1 = (m0 + 8) >> 2;
        #pragma unroll
        for (int nt = 0; nt < 8; ++nt) {
            const int n0 = nt * 8 + 2 * t;
            float* d = VD[mi * 8 + nt];
            Bd[(n0*4 + l_)*PC + c0]     = packHL(d[0]);
            Bd[((n0+1)*4 + l_)*PC + c0] = packHL(d[1]);
            Bd[(n0*4 + l_)*PC + c1]     = packHL(d[2]);
            Bd[((n0+1)*4 + l_)*PC + c1] = packHL(d[3]);
        }
    }
}

// ---------------------------------------------------------------------------
// Fused main kernel: CTA = (n, 4-l chunk)
// ---------------------------------------------------------------------------
#define SM_B1    16896                     // 8 ops * 2112 u32
#define SM_B2    (SM_B1 + 17408)           // 256 rows * 68 u32
#define SM_BIAS  (SM_B2 + 17408)
#define SMEM_BYTES ((SM_BIAS + 64) * 4)    // 207104 B

__global__ void __launch_bounds__(256, 1)
mix_main(const float* __restrict__ x, const float* __restrict__ bias,
         float* __restrict__ out)
{
    extern __shared__ u32 sm[];
    u32*   sB1   = sm + SM_B1;
    u32*   sB2   = sm + SM_B2;
    float* sBias = (float*)(sm + SM_BIAS);
    const int tid = threadIdx.x;

    // stage operator tables (padded rows)
    for (int i = tid; i < 8 * 2048; i += 256) {
        const int op = i >> 11, j = i & 2047;
        sm[op * 2112 + (j >> 5) * POP + (j & 31)] = g_opsU[i];
    }
    if (tid < 64) sBias[tid] = bias[tid];

    const int n = blockIdx.y, l0 = blockIdx.x * LB;
    const float* xn   = x   + (size_t)n * 64 * 64 * 512 + l0;
    float*       outn = out + (size_t)n * 64 * 64 * 512 + l0;

    // load + split X -> B1 rows (v*4+l), col c
    {
        const int c = tid & 63;
        #pragma unroll 1
        for (int i = 0; i < 16; ++i) {
            const int v = (tid >> 6) + 4 * i;
            const float4 f = *(const float4*)(xn + ((size_t)c * 64 + v) * 512);
            const u32 base = (u32)(v * 4) * PC + c;
            sB1[base]          = packHL(f.x);
            sB1[base + PC]     = packHL(f.y);
            sB1[base + 2 * PC] = packHL(f.z);
            sB1[base + 3 * PC] = packHL(f.w);
        }
    }
    __syncthreads();

    const int wid = tid >> 5, lane = tid & 31, g = lane >> 2, t = lane & 3;
    const u32* Ahi = sm;            const u32* Alo = sm + 2112;
    const u32* M0h = sm + 2*2112;   const u32* M0l = sm + 3*2112;
    const u32* M1h = sm + 4*2112;   const u32* M1l = sm + 5*2112;
    const u32* M2h = sm + 6*2112;   const u32* M2l = sm + 7*2112;

    float D[16][4];
    #pragma unroll
    for (int j = 0; j < 16; ++j) {
        const int n0 = (j & 7) * 8 + 2 * t;
        D[j][0] = D[j][2] = sBias[n0];
        D[j][1] = D[j][3] = sBias[n0 + 1];
    }

    // out += M0 * X ; Y1 = A * X -> B2
    gemm3<0>(M0h, M0l, sB1, D, wid, g, t);
    {
        float VD[16][4];
        #pragma unroll
        for (int j = 0; j < 16; ++j) VD[j][0] = VD[j][1] = VD[j][2] = VD[j][3] = 0.0f;
        gemm3<1>(Ahi, Alo, sB1, VD, wid, g, t);
        storeVert(sB2, VD, wid, g, t);
    }
    __syncthreads();                 // Y1 visible; X reads done

    // out += M1 * Y1 ; Y2 = A * Y1 -> B1 (X dead)
    gemm3<0>(M1h, M1l, sB2, D, wid, g, t);
    {
        float VD[16][4];
        #pragma unroll
        for (int j = 0; j < 16; ++j) VD[j][0] = VD[j][1] = VD[j][2] = VD[j][3] = 0.0f;
        gemm3<1>(Ahi, Alo, sB2, VD, wid, g, t);
        storeVert(sB1, VD, wid, g, t);
    }
    __syncthreads();                 // Y2 visible; Y1 reads done

    // out += M2 * Y2
    gemm3<0>(M2h, M2l, sB1, D, wid, g, t);

    // stage D (fp32) into B2, rows m=(v,l), col o
    {
        float* st = (float*)sB2;
        #pragma unroll
        for (int mi = 0; mi < 2; ++mi) {
            const int m0 = (wid * 2 + mi) * 16 + g;
            #pragma unroll
            for (int nt = 0; nt < 8; ++nt) {
                const int n0 = nt * 8 + 2 * t;
                float* d = D[mi * 8 + nt];
                st[m0 * PC + n0]           = d[0];
                st[m0 * PC + n0 + 1]       = d[1];
                st[(m0 + 8) * PC + n0]     = d[2];
                st[(m0 + 8) * PC + n0 + 1] = d[3];
            }
        }
    }
    __syncthreads();

    // coalesced-ish output: lane = o (conflict-free LDS), float4 along l
    {
        const float* st = (const float*)sB2;
        const int o = tid & 63;
        #pragma unroll 1
        for (int i = 0; i < 16; ++i) {
            const int v = (tid >> 6) + 4 * i;
            float4 r;
            r.x = st[(v * 4 + 0) * PC + o];
            r.y = st[(v * 4 + 1) * PC + o];
            r.z = st[(v * 4 + 2) * PC + o];
            r.w = st[(v * 4 + 3) * PC + o];
            *(float4*)(outn + ((size_t)o * 64 + v) * 512) = r;
        }
    }
}

// ---------------------------------------------------------------------------
// Launch
// ---------------------------------------------------------------------------
extern "C" void kernel_launch(void* const* d_in, const int* in_sizes, int n_in,
                              void* d_out, int out_size)
{
    (void)in_sizes; (void)n_in; (void)out_size;
    const float* x   = (const float*)d_in[0];   // [32,64,64,512]
    const float* adj = (const float*)d_in[1];   // [64,64]
    const float* W   = (const float*)d_in[2];   // [64,192]
    const float* b   = (const float*)d_in[3];   // [64]
    float*       out = (float*)d_out;           // [32,64,64,512]

    setup_kernel<<<1, 256>>>(adj, W);

    cudaFuncSetAttribute(mix_main, cudaFuncAttributeMaxDynamicSharedMemorySize, SMEM_BYTES);
    dim3 grid(512 / LB, 32);                    // 128 l-chunks x 32 n
    mix_main<<<grid, 256, SMEM_BYTES>>>(x, b, out);
}